// round 14
// baseline (speedup 1.0000x reference)
#include <cuda_runtime.h>

// Involution: B=4, H=W=56, C=256, Cr=64, G=16, Cg=16, K=7, pad=3
// Round 13: identical resubmission of R11 (previous round hit a broker/container
// infra failure; kernel never ran). rs_kernel 32px blocks; B4 f32x2 pairs.

#define HH 56
#define WWD 56
#define CC 256
#define CR 64
#define NG 16
#define CGC 16
#define KKT 49
#define NPIXT 12544
#define TILE 8
#define HALO 14
#define NPOS 196
#define KGP 49
#define RSPD 66

using u64 = unsigned long long;

__device__ __align__(16) float g_wsT[NG * KKT * CR];   // [g*49+k][d]
__device__ __align__(16) float g_rs[(size_t)NPIXT * CR];

__device__ __forceinline__ u64 pack2(float lo, float hi) {
    u64 r; asm("mov.b64 %0,{%1,%2};" : "=l"(r) : "f"(lo), "f"(hi)); return r;
}
__device__ __forceinline__ u64 fma2(u64 a, u64 b, u64 c) {
    u64 d; asm("fma.rn.f32x2 %0,%1,%2,%3;" : "=l"(d) : "l"(a), "l"(b), "l"(c)); return d;
}
__device__ __forceinline__ void unpack2(u64 v, float& lo, float& hi) {
    asm("mov.b64 {%0,%1},%2;" : "=f"(lo), "=f"(hi) : "l"(v));
}
__device__ __forceinline__ u64 lds64(unsigned a) {
    u64 v; asm("ld.shared.b64 %0,[%1];" : "=l"(v) : "r"(a)); return v;
}

// ------------------------------------------------ rs GEMM (+ overlapped transpose)
// 32-px blocks: 392 GEMM blocks + 50 transpose blocks = 442 (~3/SM, one wave)
#define RPXB 32
#define NRSBLK 392
struct SmemR {
    float xs[RPXB][68];   //  8704 B
    float ws[CR][CR];     // 16384 B
};

__global__ __launch_bounds__(256)
void rs_kernel(const float* __restrict__ x,
               const float* __restrict__ wr,
               const float* __restrict__ gamma,
               const float* __restrict__ beta,
               const float* __restrict__ mean,
               const float* __restrict__ var,
               const float* __restrict__ wspan) {
    extern __shared__ __align__(16) float smr[];
    SmemR& s = *reinterpret_cast<SmemR*>(smr);
    const int t = threadIdx.x;

    if (blockIdx.x >= NRSBLK) {
        __shared__ float ttile[32][33];
        const int bt = blockIdx.x - NRSBLK;          // 0..49
        const int tx = t & 31, ty8 = t >> 5;
        const int gk0 = (bt % 25) * 32, d0v = (bt / 25) * 32;
        #pragma unroll
        for (int r = 0; r < 32; r += 8) {
            int d = d0v + ty8 + r, gk = gk0 + tx;
            ttile[ty8 + r][tx] = (gk < KKT * NG) ? wspan[(size_t)d * (KKT * NG) + gk] : 0.f;
        }
        __syncthreads();
        #pragma unroll
        for (int r = 0; r < 32; r += 8) {
            int gk = gk0 + ty8 + r, d = d0v + tx;
            if (gk < KKT * NG) g_wsT[(size_t)gk * CR + d] = ttile[tx][ty8 + r];
        }
        return;
    }

    const int pix0 = blockIdx.x * RPXB;
    const int dt = t & 15, mt = t >> 4;
    const int d0 = dt * 4;

    float4 acc[2];
    acc[0] = make_float4(0.f, 0.f, 0.f, 0.f);
    acc[1] = make_float4(0.f, 0.f, 0.f, 0.f);

    for (int cb = 0; cb < 4; ++cb) {
        // stage x chunk: 32 px x 64 ch = 512 f4
        #pragma unroll
        for (int k = 0; k < 2; ++k) {
            int idx = t + k * 256;
            int p = idx >> 4, c = idx & 15;
            *(float4*)&s.xs[p][c * 4] =
                __ldg((const float4*)&x[(size_t)(pix0 + p) * CC + cb * 64 + c * 4]);
        }
        // stage w chunk: 64 rows x 64 d = 1024 f4
        #pragma unroll
        for (int k = 0; k < 4; ++k) {
            int idx = t + k * 256;
            int r = idx >> 4, c = idx & 15;
            *(float4*)&s.ws[r][c * 4] =
                __ldg((const float4*)&wr[(size_t)(cb * 64 + r) * CR + c * 4]);
        }
        __syncthreads();
        #pragma unroll 4
        for (int c4 = 0; c4 < 16; ++c4) {
            float4 w0 = *(float4*)&s.ws[c4 * 4 + 0][d0];
            float4 w1 = *(float4*)&s.ws[c4 * 4 + 1][d0];
            float4 w2 = *(float4*)&s.ws[c4 * 4 + 2][d0];
            float4 w3 = *(float4*)&s.ws[c4 * 4 + 3][d0];
            #pragma unroll
            for (int i = 0; i < 2; ++i) {
                float4 a = *(float4*)&s.xs[mt * 2 + i][c4 * 4];
                acc[i].x += a.x*w0.x + a.y*w1.x + a.z*w2.x + a.w*w3.x;
                acc[i].y += a.x*w0.y + a.y*w1.y + a.z*w2.y + a.w*w3.y;
                acc[i].z += a.x*w0.z + a.y*w1.z + a.z*w2.z + a.w*w3.z;
                acc[i].w += a.x*w0.w + a.y*w1.w + a.z*w2.w + a.w*w3.w;
            }
        }
        __syncthreads();
    }
    float4 gm = __ldg((const float4*)&gamma[d0]);
    float4 bt4 = __ldg((const float4*)&beta[d0]);
    float4 mn = __ldg((const float4*)&mean[d0]);
    float4 vr = __ldg((const float4*)&var[d0]);
    float4 sc, bb2;
    sc.x = gm.x * rsqrtf(vr.x + 1e-3f); bb2.x = bt4.x - mn.x * sc.x;
    sc.y = gm.y * rsqrtf(vr.y + 1e-3f); bb2.y = bt4.y - mn.y * sc.y;
    sc.z = gm.z * rsqrtf(vr.z + 1e-3f); bb2.z = bt4.z - mn.z * sc.z;
    sc.w = gm.w * rsqrtf(vr.w + 1e-3f); bb2.w = bt4.w - mn.w * sc.w;
    #pragma unroll
    for (int i = 0; i < 2; ++i) {
        float4 v;
        v.x = fmaxf(acc[i].x * sc.x + bb2.x, 0.f);
        v.y = fmaxf(acc[i].y * sc.y + bb2.y, 0.f);
        v.z = fmaxf(acc[i].z * sc.z + bb2.z, 0.f);
        v.w = fmaxf(acc[i].w * sc.w + bb2.w, 0.f);
        *(float4*)&g_rs[(size_t)(pix0 + mt * 2 + i) * CR + d0] = v;
    }
}

// ------------------------------------------------ main
struct SmemM {
    float  rsP[CR][RSPD];         // 16896 B  rs transposed [d][px]
    float4 xh4[2][4][NPOS];       // 25088 B  halo [g][c4][pos]
    float  kg[2][64][KGP];        // 25088 B  [g][px][k], pad 49 (odd)
};                                // 67072 B -> 3 CTAs/SM

__global__ __launch_bounds__(256, 3)
void inv_main(const float* __restrict__ x,
              const float* __restrict__ b_span,
              float* __restrict__ out) {
    extern __shared__ __align__(16) float smf[];
    SmemM& s = *reinterpret_cast<SmemM*>(smf);
    const int t = threadIdx.x;
    const int w0 = blockIdx.x * TILE, h0 = blockIdx.y * TILE;
    const int bb = blockIdx.z >> 1, ghalf = blockIdx.z & 1;
    const size_t pixbase = ((size_t)bb * HH + h0) * WWD + w0;

    // prologue: stage rs transposed [d][px]
    #pragma unroll
    for (int k = 0; k < 4; ++k) {
        int i = t + k * 256;
        int px = i & 63, c = i >> 6;
        int py = px >> 3, pxl = px & 7;
        size_t pix = pixbase + (size_t)py * WWD + pxl;
        float4 v = __ldg((const float4*)&g_rs[pix * CR + c * 4]);
        s.rsP[c * 4 + 0][px] = v.x;
        s.rsP[c * 4 + 1][px] = v.y;
        s.rsP[c * 4 + 2][px] = v.z;
        s.rsP[c * 4 + 3][px] = v.w;
    }
    __syncthreads();

    const unsigned rs_base = (unsigned)__cvta_generic_to_shared(&s.rsP[0][0]);

    for (int it = 0; it < 4; ++it) {
        const int gA = ghalf * 8 + it * 2;

        // ---- phase 1: halo load (all threads; LDG hidden behind B3 FMA) ----
        for (int i = t; i < 2 * NPOS * 4; i += 256) {
            int g, rem;
            if (i >= 784) { g = 1; rem = i - 784; } else { g = 0; rem = i; }
            int pos = rem >> 2, q = rem & 3;
            int hh = pos / HALO, ww = pos - hh * HALO;
            int h = h0 + hh - 3, w = w0 + ww - 3;
            float4 v = make_float4(0.f, 0.f, 0.f, 0.f);
            if (h >= 0 && h < HH && w >= 0 && w < WWD)
                v = __ldg((const float4*)&x[(((size_t)bb * HH + h) * WWD + w) * CC
                                            + (gA + g) * CGC + q * 4]);
            s.xh4[g][q][pos] = v;
        }

        // ---- B3: kg = rs @ wsT + bias, f32x2 over pixel pairs (224 thr) ----
        if (t < 224) {
            const int g = t / 112, r = t - g * 112;
            const int pp = r & 15, kgi = r >> 4;
            const int k0 = kgi * 7;
            const int gg = gA + g;
            const float* wrow = g_wsT + (size_t)(gg * KKT + k0) * CR;
            const float* bs = b_span + gg * KKT + k0;
            u64 acc2[2][7];
            #pragma unroll
            for (int j = 0; j < 7; ++j) {
                float bv = __ldg(&bs[j]);
                u64 b2 = pack2(bv, bv);
                acc2[0][j] = b2; acc2[1][j] = b2;
            }
            const unsigned o0 = (unsigned)(2 * pp) * 4u;
            const unsigned o1 = (unsigned)(2 * (pp + 16)) * 4u;
            #pragma unroll 2
            for (int d4 = 0; d4 < 16; ++d4) {
                u64 ra[4], rb[4];
                #pragma unroll
                for (int dd = 0; dd < 4; ++dd) {
                    unsigned rowa = rs_base + (unsigned)((d4 * 4 + dd) * RSPD) * 4u;
                    ra[dd] = lds64(rowa + o0);
                    rb[dd] = lds64(rowa + o1);
                }
                #pragma unroll
                for (int j = 0; j < 7; ++j) {
                    float4 w4 = __ldg((const float4*)&wrow[j * CR + d4 * 4]);
                    u64 w2;
                    w2 = pack2(w4.x, w4.x);
                    acc2[0][j] = fma2(ra[0], w2, acc2[0][j]);
                    acc2[1][j] = fma2(rb[0], w2, acc2[1][j]);
                    w2 = pack2(w4.y, w4.y);
                    acc2[0][j] = fma2(ra[1], w2, acc2[0][j]);
                    acc2[1][j] = fma2(rb[1], w2, acc2[1][j]);
                    w2 = pack2(w4.z, w4.z);
                    acc2[0][j] = fma2(ra[2], w2, acc2[0][j]);
                    acc2[1][j] = fma2(rb[2], w2, acc2[1][j]);
                    w2 = pack2(w4.w, w4.w);
                    acc2[0][j] = fma2(ra[3], w2, acc2[0][j]);
                    acc2[1][j] = fma2(rb[3], w2, acc2[1][j]);
                }
            }
            #pragma unroll
            for (int i = 0; i < 2; ++i) {
                const int px = 2 * (pp + 16 * i);
                #pragma unroll
                for (int j = 0; j < 7; ++j) {
                    float lo, hi;
                    unpack2(acc2[i][j], lo, hi);
                    s.kg[g][px][k0 + j] = lo;
                    s.kg[g][px + 1][k0 + j] = hi;
                }
            }
        }
        __syncthreads();

        // ---- B4: 2-px column, 8-row sliding window, f32x2 channel pairs ----
        {
            const int g = t >> 7, r = t & 127;
            const int pyq = r >> 5, rr = r & 31;
            const int c4 = rr >> 3, pxl = rr & 7;
            const int py0 = pyq * 2;
            const u64 z2 = pack2(0.f, 0.f);
            u64 a0xy = z2, a0zw = z2, a1xy = z2, a1zw = z2;
            const float4* xcol = &s.xh4[g][c4][0];
            const float* kg0 = &s.kg[g][py0 * 8 + pxl][0];
            const float* kg1 = &s.kg[g][(py0 + 1) * 8 + pxl][0];
            #pragma unroll
            for (int rr8 = 0; rr8 < 8; ++rr8) {
                const int row = py0 + rr8;
                u64 xy[7], zw[7];
                #pragma unroll
                for (int kw = 0; kw < 7; ++kw) {
                    float4 xv = xcol[row * HALO + pxl + kw];
                    xy[kw] = pack2(xv.x, xv.y);
                    zw[kw] = pack2(xv.z, xv.w);
                }
                if (rr8 <= 6) {
                    const float* kgr = kg0 + rr8 * 7;
                    #pragma unroll
                    for (int kw = 0; kw < 7; ++kw) {
                        u64 k2 = pack2(kgr[kw], kgr[kw]);
                        a0xy = fma2(xy[kw], k2, a0xy);
                        a0zw = fma2(zw[kw], k2, a0zw);
                    }
                }
                if (rr8 >= 1) {
                    const float* kgr = kg1 + (rr8 - 1) * 7;
                    #pragma unroll
                    for (int kw = 0; kw < 7; ++kw) {
                        u64 k2 = pack2(kgr[kw], kgr[kw]);
                        a1xy = fma2(xy[kw], k2, a1xy);
                        a1zw = fma2(zw[kw], k2, a1zw);
                    }
                }
            }
            float4 a0, a1;
            unpack2(a0xy, a0.x, a0.y); unpack2(a0zw, a0.z, a0.w);
            unpack2(a1xy, a1.x, a1.y); unpack2(a1zw, a1.z, a1.w);
            size_t o = (pixbase + (size_t)py0 * WWD + pxl) * CC + (gA + g) * CGC + c4 * 4;
            *(float4*)&out[o] = a0;
            *(float4*)&out[o + (size_t)WWD * CC] = a1;
        }
        __syncthreads();
    }
}

// ------------------------------------------------ launch
extern "C" void kernel_launch(void* const* d_in, const int* in_sizes, int n_in,
                              void* d_out, int out_size) {
    (void)in_sizes; (void)n_in; (void)out_size;
    const float* x        = (const float*)d_in[0];
    const float* w_reduce = (const float*)d_in[1];
    const float* gamma    = (const float*)d_in[2];
    const float* beta     = (const float*)d_in[3];
    const float* mean     = (const float*)d_in[4];
    const float* var      = (const float*)d_in[5];
    const float* w_span   = (const float*)d_in[6];
    const float* b_span   = (const float*)d_in[7];
    float* out = (float*)d_out;

    cudaFuncSetAttribute(rs_kernel, cudaFuncAttributeMaxDynamicSharedMemorySize,
                         (int)sizeof(SmemR));
    cudaFuncSetAttribute(inv_main, cudaFuncAttributeMaxDynamicSharedMemorySize,
                         (int)sizeof(SmemM));

    rs_kernel<<<NRSBLK + 50, 256, sizeof(SmemR)>>>(x, w_reduce, gamma, beta,
                                                   mean, var, w_span);
    dim3 grid(WWD / TILE, HH / TILE, 8);   // (7, 7, 8) = 392 CTAs
    inv_main<<<grid, 256, sizeof(SmemM)>>>(x, b_span, out);
}